// round 1
// baseline (speedup 1.0000x reference)
#include <cuda_runtime.h>

#define THRESHOLD 0.5f
#define B 256
#define HW 49          // 7*7
#define C_INTERM 1000
#define C_VGG 512

// Scratch: thresholded CAM value per (batch, spatial) cell. 12544 floats.
__device__ float g_tvals[B * HW];

// ---------------------------------------------------------------------------
// Kernel 1: per-batch argmax over branchA_end[b, 0:1000] (first-index wins),
// then gather interm[b, hw, idx] for hw in [0,49), threshold, store scratch.
// One block per batch.
// ---------------------------------------------------------------------------
__global__ __launch_bounds__(256) void argmax_gather_kernel(
    const float* __restrict__ branchA,   // [B, 1000]
    const float* __restrict__ interm)    // [B, 49, 1000]
{
    const int b   = blockIdx.x;
    const int tid = threadIdx.x;

    const float* row = branchA + (size_t)b * C_INTERM;

    // Each thread scans a strided slice; first-index-wins ties.
    float best_v = -__FLT_MAX__;
    int   best_i = C_INTERM;  // sentinel larger than any real index
    #pragma unroll
    for (int i = tid; i < C_INTERM; i += 256) {
        float v = row[i];
        if (v > best_v || (v == best_v && i < best_i)) {
            best_v = v;
            best_i = i;
        }
    }

    __shared__ float s_v[256];
    __shared__ int   s_i[256];
    s_v[tid] = best_v;
    s_i[tid] = best_i;
    __syncthreads();

    // Tree reduction, first-index-wins on equal values.
    for (int off = 128; off > 0; off >>= 1) {
        if (tid < off) {
            float ov = s_v[tid + off];
            int   oi = s_i[tid + off];
            if (ov > s_v[tid] || (ov == s_v[tid] && oi < s_i[tid])) {
                s_v[tid] = ov;
                s_i[tid] = oi;
            }
        }
        __syncthreads();
    }

    const int idx = s_i[0];

    // Gather + threshold for the 49 spatial cells of this batch.
    if (tid < HW) {
        float a = __ldg(interm + ((size_t)b * HW + tid) * C_INTERM + idx);
        g_tvals[b * HW + tid] = (a > THRESHOLD) ? a : 0.0f;
    }
}

// ---------------------------------------------------------------------------
// Kernel 2: out[b,hw,c] = vgg_end[b,hw,c] - t[b,hw], float4-vectorized.
// 512 floats (128 float4) per (b,hw) cell, innermost and contiguous.
// ---------------------------------------------------------------------------
__global__ __launch_bounds__(256) void subtract_kernel(
    const float4* __restrict__ vgg,   // [B*HW*512/4]
    float4* __restrict__ out)
{
    const int n4 = B * HW * C_VGG / 4;  // 1,605,632
    int i = blockIdx.x * blockDim.x + threadIdx.x;
    if (i >= n4) return;

    // 128 float4 per (b,hw) cell
    const float t = g_tvals[i >> 7];

    float4 v = vgg[i];
    v.x -= t; v.y -= t; v.z -= t; v.w -= t;
    out[i] = v;
}

extern "C" void kernel_launch(void* const* d_in, const int* in_sizes, int n_in,
                              void* d_out, int out_size) {
    const float* vgg_end    = (const float*)d_in[0];  // [256,7,7,512]
    const float* interm     = (const float*)d_in[1];  // [256,7,7,1000]
    const float* branchA    = (const float*)d_in[2];  // [256,1000]
    float*       out        = (float*)d_out;

    argmax_gather_kernel<<<B, 256>>>(branchA, interm);

    const int n4 = B * HW * C_VGG / 4;
    const int blocks = (n4 + 255) / 256;  // 6272
    subtract_kernel<<<blocks, 256>>>((const float4*)vgg_end, (float4*)out);
}